// round 4
// baseline (speedup 1.0000x reference)
#include <cuda_runtime.h>
#include <cuda_bf16.h>
#include <cstdint>

#define N_FEAT4 16     // float4 per row (64 floats)

// ---------------------------------------------------------------------------
// Inline int64-vs-int32 detection: if the index buffer is int64 with values
// < 50000, every odd 32-bit word is the zero high half. 8 samples ->
// false-positive probability with int32 data ~ (1/50000)^8 ~ 2.6e-38.
// ---------------------------------------------------------------------------
__device__ __forceinline__ bool idx_is64(const void* idx_raw) {
    const unsigned int* w = (const unsigned int*)idx_raw;
    unsigned int acc = w[1] | w[3] | w[5] | w[7] | w[9] | w[11] | w[13] | w[15];
    return acc == 0u;
}

// ---------------------------------------------------------------------------
// Kernel 1: zero the output (harness poisons it with 0xAA).
// ---------------------------------------------------------------------------
__global__ void zero_out_kernel(float4* __restrict__ out, int n_vec4) {
    int i = blockIdx.x * blockDim.x + threadIdx.x;
    if (i < n_vec4) out[i] = make_float4(0.f, 0.f, 0.f, 0.f);
}

__device__ __forceinline__ void red_v4(float* dst, float4 v) {
    asm volatile("red.global.add.v4.f32 [%0], {%1, %2, %3, %4};"
                 :: "l"(dst), "f"(v.x), "f"(v.y), "f"(v.z), "f"(v.w) : "memory");
}

// ---------------------------------------------------------------------------
// Kernel 2: scatter-add. Each 16-lane group handles 8 consecutive rows per
// iteration. Per lane: 8 streaming LDG.128 (128B in flight) + vectorized
// index loads, then 8 red.global.add.v4.f32 (no return). Main loop is
// predicate-free; tail rows (n_rows % 8) go through a scalar loop.
// ---------------------------------------------------------------------------
__global__ void __launch_bounds__(256)
aggr_kernel(const float4* __restrict__ in,
            const void* __restrict__ idx_raw,
            float* __restrict__ out,
            int n_rows) {
    const bool is64 = idx_is64(idx_raw);

    const int group   = (blockIdx.x * blockDim.x + threadIdx.x) >> 4;
    const int lane    = threadIdx.x & 15;
    const int ngroups = (gridDim.x * blockDim.x) >> 4;
    const int n_main  = n_rows & ~7;

    for (int base = group * 8; base < n_main; base += ngroups * 8) {
        // ---- vectorized index loads (base is a multiple of 8 -> aligned) ----
        int s0, s1, s2, s3, s4, s5, s6, s7;
        if (!is64) {
            const int4* ip = (const int4*)((const int*)idx_raw + base);
            int4 a = __ldcs(ip);
            int4 b = __ldcs(ip + 1);
            s0 = a.x; s1 = a.y; s2 = a.z; s3 = a.w;
            s4 = b.x; s5 = b.y; s6 = b.z; s7 = b.w;
        } else {
            const int4* ip = (const int4*)((const long long*)idx_raw + base);
            int4 a = __ldcs(ip);
            int4 b = __ldcs(ip + 1);
            int4 c = __ldcs(ip + 2);
            int4 d = __ldcs(ip + 3);
            s0 = a.x; s1 = a.z; s2 = b.x; s3 = b.z;
            s4 = c.x; s5 = c.z; s6 = d.x; s7 = d.z;
        }

        // ---- 8 batched streaming row loads (256B contiguous per row) ----
        const float4* p = in + base * N_FEAT4 + lane;
        float4 v0 = __ldcs(p);
        float4 v1 = __ldcs(p + 1 * N_FEAT4);
        float4 v2 = __ldcs(p + 2 * N_FEAT4);
        float4 v3 = __ldcs(p + 3 * N_FEAT4);
        float4 v4 = __ldcs(p + 4 * N_FEAT4);
        float4 v5 = __ldcs(p + 5 * N_FEAT4);
        float4 v6 = __ldcs(p + 6 * N_FEAT4);
        float4 v7 = __ldcs(p + 7 * N_FEAT4);

        // ---- 8 no-return reductions ----
        const int l4 = lane * 4;
        red_v4(out + s0 * 64 + l4, v0);
        red_v4(out + s1 * 64 + l4, v1);
        red_v4(out + s2 * 64 + l4, v2);
        red_v4(out + s3 * 64 + l4, v3);
        red_v4(out + s4 * 64 + l4, v4);
        red_v4(out + s5 * 64 + l4, v5);
        red_v4(out + s6 * 64 + l4, v6);
        red_v4(out + s7 * 64 + l4, v7);
    }

    // ---- tail (n_rows % 8 rows; usually empty) ----
    for (int r = n_main + group; r < n_rows; r += ngroups) {
        int seg = is64 ? (int)((const long long*)idx_raw)[r]
                       : ((const int*)idx_raw)[r];
        float4 v = __ldcs(&in[r * N_FEAT4 + lane]);
        red_v4(out + seg * 64 + lane * 4, v);
    }
}

// ---------------------------------------------------------------------------
// Launch
// ---------------------------------------------------------------------------
extern "C" void kernel_launch(void* const* d_in, const int* in_sizes, int n_in,
                              void* d_out, int out_size) {
    const float4* in  = (const float4*)d_in[0];
    const void*   idx = (const void*)d_in[1];
    float*        out = (float*)d_out;

    const int n_rows = in_sizes[0] / 64;    // 1,600,000

    const int n_vec4 = out_size / 4;        // 3.2M floats -> 800K float4
    zero_out_kernel<<<(n_vec4 + 255) / 256, 256>>>((float4*)d_out, n_vec4);

    // ~2 waves at expected occupancy; grid-stride keeps balance.
    const int blocks = 1184;
    aggr_kernel<<<blocks, 256>>>(in, idx, out, n_rows);
}

// round 5
// speedup vs baseline: 1.0003x; 1.0003x over previous
#include <cuda_runtime.h>
#include <cuda_bf16.h>
#include <cstdint>

#define N_SEGMENTS 50000
#define N_FEAT4    16          // float4 per row (64 floats)
#define CAP        64          // bucket capacity (Poisson(32): P(>64) ~ 1e-7/seg; overflow list keeps it correct)
#define OVF_MAX    (1 << 20)

// ---------------------------------------------------------------------------
// Static device scratch (no allocations allowed).
// ---------------------------------------------------------------------------
__device__ int g_cnt[N_SEGMENTS];
__device__ int g_bucket[N_SEGMENTS * CAP];   // 12.8 MB, L2-resident
__device__ int g_ovf_n;
__device__ int g_ovf[OVF_MAX];

__device__ __forceinline__ bool idx_is64(const void* idx_raw) {
    const unsigned int* w = (const unsigned int*)idx_raw;
    unsigned int acc = w[1] | w[3] | w[5] | w[7] | w[9] | w[11] | w[13] | w[15];
    return acc == 0u;
}

__device__ __forceinline__ float4 add4(float4 a, float4 b) {
    return make_float4(a.x + b.x, a.y + b.y, a.z + b.z, a.w + b.w);
}

// ---------------------------------------------------------------------------
// Kernel 1: zero counters + overflow count.
// ---------------------------------------------------------------------------
__global__ void zero_cnt_kernel() {
    int i = blockIdx.x * blockDim.x + threadIdx.x;
    if (i < N_SEGMENTS) g_cnt[i] = 0;
    if (i == 0) g_ovf_n = 0;
}

// ---------------------------------------------------------------------------
// Kernel 2: scatter row ids into per-segment buckets. 4 rows per thread,
// vectorized index loads.
// ---------------------------------------------------------------------------
__global__ void __launch_bounds__(256)
scatter_idx_kernel(const void* __restrict__ idx_raw, int n_rows) {
    const bool is64 = idx_is64(idx_raw);
    const int base = (blockIdx.x * blockDim.x + threadIdx.x) * 4;
    if (base >= n_rows) return;

    int s[4];
    const int cnt = min(4, n_rows - base);
    if (cnt == 4) {
        if (!is64) {
            int4 a = *(const int4*)((const int*)idx_raw + base);
            s[0] = a.x; s[1] = a.y; s[2] = a.z; s[3] = a.w;
        } else {
            const int4* ip = (const int4*)((const long long*)idx_raw + base);
            int4 a = ip[0], b = ip[1];
            s[0] = a.x; s[1] = a.z; s[2] = b.x; s[3] = b.z;
        }
    } else {
        for (int k = 0; k < cnt; ++k)
            s[k] = is64 ? (int)((const long long*)idx_raw)[base + k]
                        : ((const int*)idx_raw)[base + k];
    }

    #pragma unroll
    for (int k = 0; k < 4; ++k) {
        if (k < cnt) {
            int slot = atomicAdd(&g_cnt[s[k]], 1);
            if (slot < CAP) {
                g_bucket[s[k] * CAP + slot] = base + k;
            } else {
                int o = atomicAdd(&g_ovf_n, 1);
                if (o < OVF_MAX) g_ovf[o] = base + k;
            }
        }
    }
}

// ---------------------------------------------------------------------------
// Kernel 3: gather-sum. One WARP per segment; lane = (row half, col).
// 8 rows per iteration -> 4 independent LDG.128 per lane in flight.
// Register accumulation (zero atomics), halves combined via shuffle,
// single coalesced STG.128 per segment (covers the 0xAA poison too).
// ---------------------------------------------------------------------------
__global__ void __launch_bounds__(256)
gather_kernel(const float4* __restrict__ in, float4* __restrict__ out) {
    const int warp = (blockIdx.x * blockDim.x + threadIdx.x) >> 5;
    if (warp >= N_SEGMENTS) return;
    const int lane = threadIdx.x & 31;
    const int half = lane >> 4;      // which of the 2 rows per step
    const int col  = lane & 15;      // float4 column within the row

    int n = g_cnt[warp];
    if (n > CAP) n = CAP;
    const int* bk = g_bucket + warp * CAP;

    float4 acc = make_float4(0.f, 0.f, 0.f, 0.f);

    int i = 0;
    for (; i + 8 <= n; i += 8) {
        // bucket reads hit L2 (scratch is L2-resident); 2 distinct addrs/warp
        int r0 = bk[i + 0 + half];
        int r1 = bk[i + 2 + half];
        int r2 = bk[i + 4 + half];
        int r3 = bk[i + 6 + half];
        float4 v0 = __ldg(&in[r0 * N_FEAT4 + col]);
        float4 v1 = __ldg(&in[r1 * N_FEAT4 + col]);
        float4 v2 = __ldg(&in[r2 * N_FEAT4 + col]);
        float4 v3 = __ldg(&in[r3 * N_FEAT4 + col]);
        acc = add4(acc, add4(add4(v0, v1), add4(v2, v3)));
    }
    for (; i + 2 <= n; i += 2) {
        int r = bk[i + half];
        acc = add4(acc, __ldg(&in[r * N_FEAT4 + col]));
    }
    if (i < n && half == 0) {
        acc = add4(acc, __ldg(&in[bk[i] * N_FEAT4 + col]));
    }

    // combine the two row-halves
    acc.x += __shfl_xor_sync(0xffffffffu, acc.x, 16);
    acc.y += __shfl_xor_sync(0xffffffffu, acc.y, 16);
    acc.z += __shfl_xor_sync(0xffffffffu, acc.z, 16);
    acc.w += __shfl_xor_sync(0xffffffffu, acc.w, 16);

    if (half == 0) out[warp * N_FEAT4 + col] = acc;
}

// ---------------------------------------------------------------------------
// Kernel 4: overflow fixup (normally 0 entries). RED on top of gather stores.
// ---------------------------------------------------------------------------
__global__ void __launch_bounds__(256)
overflow_kernel(const float4* __restrict__ in, const void* __restrict__ idx_raw,
                float* __restrict__ out) {
    int cnt = g_ovf_n;
    if (cnt <= 0) return;
    if (cnt > OVF_MAX) cnt = OVF_MAX;

    const bool is64 = idx_is64(idx_raw);
    int t    = blockIdx.x * blockDim.x + threadIdx.x;
    int lane = t & 15;
    int e    = t >> 4;
    int estr = (gridDim.x * blockDim.x) >> 4;

    for (; e < cnt; e += estr) {
        int r   = g_ovf[e];
        int seg = is64 ? (int)((const long long*)idx_raw)[r]
                       : ((const int*)idx_raw)[r];
        float4 v = in[r * N_FEAT4 + lane];
        float* dst = out + (long long)seg * 64 + lane * 4;
        asm volatile("red.global.add.v4.f32 [%0], {%1, %2, %3, %4};"
                     :: "l"(dst), "f"(v.x), "f"(v.y), "f"(v.z), "f"(v.w) : "memory");
    }
}

// ---------------------------------------------------------------------------
// Launch
// ---------------------------------------------------------------------------
extern "C" void kernel_launch(void* const* d_in, const int* in_sizes, int n_in,
                              void* d_out, int out_size) {
    const float4* in  = (const float4*)d_in[0];
    const void*   idx = (const void*)d_in[1];

    const int n_rows = in_sizes[0] / 64;    // 1,600,000

    zero_cnt_kernel<<<(N_SEGMENTS + 255) / 256, 256>>>();

    const int sthreads = (n_rows + 3) / 4;
    scatter_idx_kernel<<<(sthreads + 255) / 256, 256>>>(idx, n_rows);

    // one warp per segment, 8 warps per block
    gather_kernel<<<(N_SEGMENTS + 7) / 8, 256>>>(in, (float4*)d_out);

    overflow_kernel<<<32, 256>>>(in, idx, (float*)d_out);
}

// round 6
// speedup vs baseline: 1.0109x; 1.0106x over previous
#include <cuda_runtime.h>
#include <cuda_bf16.h>
#include <cstdint>

#define N_SEGMENTS 50000
#define N_FEAT4    16          // float4 per row (64 floats)
#define CAP        64          // Poisson(32): P(>64) ~ 1e-8/seg; overflow list keeps correctness
#define OVF_MAX    (1 << 20)

// ---------------------------------------------------------------------------
// Static device scratch (no allocations allowed).
// ---------------------------------------------------------------------------
__device__ int g_cnt[N_SEGMENTS];
__device__ int g_bucket[N_SEGMENTS * CAP];   // 12.8 MB, L2-resident
__device__ int g_ovf_n;
__device__ int g_ovf[OVF_MAX];

__device__ __forceinline__ bool idx_is64(const void* idx_raw) {
    const unsigned int* w = (const unsigned int*)idx_raw;
    unsigned int acc = w[1] | w[3] | w[5] | w[7] | w[9] | w[11] | w[13] | w[15];
    return acc == 0u;
}

__device__ __forceinline__ float4 add4(float4 a, float4 b) {
    return make_float4(a.x + b.x, a.y + b.y, a.z + b.z, a.w + b.w);
}

// ---------------------------------------------------------------------------
// Kernel 1: zero counters + overflow count.
// ---------------------------------------------------------------------------
__global__ void zero_cnt_kernel() {
    int i = blockIdx.x * blockDim.x + threadIdx.x;
    if (i < N_SEGMENTS) g_cnt[i] = 0;
    if (i == 0) g_ovf_n = 0;
}

// ---------------------------------------------------------------------------
// Kernel 2: scatter row ids into per-segment buckets. 4 rows per thread,
// vectorized index loads.
// ---------------------------------------------------------------------------
__global__ void __launch_bounds__(256)
scatter_idx_kernel(const void* __restrict__ idx_raw, int n_rows) {
    const bool is64 = idx_is64(idx_raw);
    const int base = (blockIdx.x * blockDim.x + threadIdx.x) * 4;
    if (base >= n_rows) return;

    int s[4];
    const int cnt = min(4, n_rows - base);
    if (cnt == 4) {
        if (!is64) {
            int4 a = __ldcs((const int4*)((const int*)idx_raw + base));
            s[0] = a.x; s[1] = a.y; s[2] = a.z; s[3] = a.w;
        } else {
            const int4* ip = (const int4*)((const long long*)idx_raw + base);
            int4 a = __ldcs(ip), b = __ldcs(ip + 1);
            s[0] = a.x; s[1] = a.z; s[2] = b.x; s[3] = b.z;
        }
    } else {
        for (int k = 0; k < cnt; ++k)
            s[k] = is64 ? (int)((const long long*)idx_raw)[base + k]
                        : ((const int*)idx_raw)[base + k];
    }

    #pragma unroll
    for (int k = 0; k < 4; ++k) {
        if (k < cnt) {
            int slot = atomicAdd(&g_cnt[s[k]], 1);
            if (slot < CAP) {
                g_bucket[s[k] * CAP + slot] = base + k;
            } else {
                int o = atomicAdd(&g_ovf_n, 1);
                if (o < OVF_MAX) g_ovf[o] = base + k;
            }
        }
    }
}

// ---------------------------------------------------------------------------
// Kernel 3: gather-sum. One WARP per segment.
// Bucket ids are prefetched into SMEM with 2 coalesced loads (one-time L2
// latency); the hot loop's row ids come from LDS, so the random DRAM row
// loads form no dependency chain and pipeline deeply (8 LDG.128 in flight
// per lane = 4KB/warp). Register accumulation, shuffle-combine halves,
// one coalesced STG.128 per segment (clears the 0xAA poison too).
// ---------------------------------------------------------------------------
__global__ void __launch_bounds__(256)
gather_kernel(const float4* __restrict__ in, float4* __restrict__ out) {
    __shared__ int sm_bk[8][CAP];

    const int wblk = threadIdx.x >> 5;
    const int warp = blockIdx.x * 8 + wblk;
    if (warp >= N_SEGMENTS) return;
    const int lane = threadIdx.x & 31;
    const int half = lane >> 4;      // which of 2 rows per step
    const int col  = lane & 15;      // float4 column within the row

    int n = g_cnt[warp];
    if (n > CAP) n = CAP;
    const int* bk = g_bucket + warp * CAP;

    // Prefetch the whole bucket (coalesced, L2-resident scratch).
    sm_bk[wblk][lane]      = bk[lane];
    sm_bk[wblk][lane + 32] = bk[lane + 32];
    __syncwarp();
    const int* sbk = sm_bk[wblk];

    float4 acc0 = make_float4(0.f, 0.f, 0.f, 0.f);
    float4 acc1 = acc0;

    int i = 0;
    for (; i + 16 <= n; i += 16) {
        int r0 = sbk[i +  0 + half];
        int r1 = sbk[i +  2 + half];
        int r2 = sbk[i +  4 + half];
        int r3 = sbk[i +  6 + half];
        int r4 = sbk[i +  8 + half];
        int r5 = sbk[i + 10 + half];
        int r6 = sbk[i + 12 + half];
        int r7 = sbk[i + 14 + half];
        float4 v0 = __ldcs(&in[r0 * N_FEAT4 + col]);
        float4 v1 = __ldcs(&in[r1 * N_FEAT4 + col]);
        float4 v2 = __ldcs(&in[r2 * N_FEAT4 + col]);
        float4 v3 = __ldcs(&in[r3 * N_FEAT4 + col]);
        float4 v4 = __ldcs(&in[r4 * N_FEAT4 + col]);
        float4 v5 = __ldcs(&in[r5 * N_FEAT4 + col]);
        float4 v6 = __ldcs(&in[r6 * N_FEAT4 + col]);
        float4 v7 = __ldcs(&in[r7 * N_FEAT4 + col]);
        acc0 = add4(acc0, add4(add4(v0, v1), add4(v2, v3)));
        acc1 = add4(acc1, add4(add4(v4, v5), add4(v6, v7)));
    }
    for (; i + 2 <= n; i += 2) {
        acc0 = add4(acc0, __ldcs(&in[sbk[i + half] * N_FEAT4 + col]));
    }
    if (i < n && half == 0) {
        acc0 = add4(acc0, __ldcs(&in[sbk[i] * N_FEAT4 + col]));
    }

    float4 acc = add4(acc0, acc1);
    acc.x += __shfl_xor_sync(0xffffffffu, acc.x, 16);
    acc.y += __shfl_xor_sync(0xffffffffu, acc.y, 16);
    acc.z += __shfl_xor_sync(0xffffffffu, acc.z, 16);
    acc.w += __shfl_xor_sync(0xffffffffu, acc.w, 16);

    if (half == 0) out[warp * N_FEAT4 + col] = acc;
}

// ---------------------------------------------------------------------------
// Kernel 4: overflow fixup (normally 0 entries). RED on top of gather stores.
// ---------------------------------------------------------------------------
__global__ void __launch_bounds__(256)
overflow_kernel(const float4* __restrict__ in, const void* __restrict__ idx_raw,
                float* __restrict__ out) {
    int cnt = g_ovf_n;
    if (cnt <= 0) return;
    if (cnt > OVF_MAX) cnt = OVF_MAX;

    const bool is64 = idx_is64(idx_raw);
    int t    = blockIdx.x * blockDim.x + threadIdx.x;
    int lane = t & 15;
    int e    = t >> 4;
    int estr = (gridDim.x * blockDim.x) >> 4;

    for (; e < cnt; e += estr) {
        int r   = g_ovf[e];
        int seg = is64 ? (int)((const long long*)idx_raw)[r]
                       : ((const int*)idx_raw)[r];
        float4 v = in[r * N_FEAT4 + lane];
        float* dst = out + (long long)seg * 64 + lane * 4;
        asm volatile("red.global.add.v4.f32 [%0], {%1, %2, %3, %4};"
                     :: "l"(dst), "f"(v.x), "f"(v.y), "f"(v.z), "f"(v.w) : "memory");
    }
}

// ---------------------------------------------------------------------------
// Launch
// ---------------------------------------------------------------------------
extern "C" void kernel_launch(void* const* d_in, const int* in_sizes, int n_in,
                              void* d_out, int out_size) {
    const float4* in  = (const float4*)d_in[0];
    const void*   idx = (const void*)d_in[1];

    const int n_rows = in_sizes[0] / 64;    // 1,600,000

    zero_cnt_kernel<<<(N_SEGMENTS + 255) / 256, 256>>>();

    const int sthreads = (n_rows + 3) / 4;
    scatter_idx_kernel<<<(sthreads + 255) / 256, 256>>>(idx, n_rows);

    // one warp per segment, 8 warps per block
    gather_kernel<<<(N_SEGMENTS + 7) / 8, 256>>>(in, (float4*)d_out);

    overflow_kernel<<<32, 256>>>(in, idx, (float*)d_out);
}